// round 1
// baseline (speedup 1.0000x reference)
#include <cuda_runtime.h>
#include <math.h>

#define NN 32
#define MM 100
#define KK 500
#define EE 50
#define SU_C 1000.0f
#define SL_C 0.0f
#define TU_C 500.0f
#define TL_C 0.0f
#define R_EARTH_C 6371.0f
#define DEG2RAD 0.017453292519943295f

__global__ __launch_bounds__(256) void embed_kernel(
    const int* __restrict__ traj_loc,   // (N, M)
    const float* __restrict__ poi,      // (LOC, 2)
    const float* __restrict__ vec,      // (N, M)
    const int* __restrict__ traj_len,   // (N,)
    const int* __restrict__ cand,       // (N, K)
    const float* __restrict__ emb_su,   // (2, E)
    const float* __restrict__ emb_sl,   // (2, E)
    const float* __restrict__ emb_tu,   // (2, E)
    const float* __restrict__ emb_tl,   // (2, E)
    float* __restrict__ out)            // (N, M, K, E)
{
    const int nm = blockIdx.x;          // 0 .. N*M-1
    const int n = nm / MM;
    const int m = nm - n * MM;
    const int tid = threadIdx.x;

    __shared__ float sC[EE];
    __shared__ float sB[EE];
    __shared__ float sds[KK];

    // ---- per-(n,m) scalars ----
    const int loc1 = traj_loc[nm];
    const float lat1 = poi[2 * loc1]     * DEG2RAD;
    const float lon1 = poi[2 * loc1 + 1] * DEG2RAD;
    float sin_unused, cos_lat1;
    __sincosf(lat1, &sin_unused, &cos_lat1);
    // use accurate cosf for safety (values small, but match fp32 ref closely)
    cos_lat1 = cosf(lat1);

    const int maskv = (m < traj_len[n]) ? 1 : 0;
    const float dt = vec[nm];

    // ---- phase 1a: coefficients C[e], B[e] ----
    if (tid < EE) {
        const float esl = emb_sl[maskv * EE + tid];
        const float esu = emb_su[maskv * EE + tid];
        const float etl = emb_tl[maskv * EE + tid];
        const float etu = emb_tu[maskv * EE + tid];
        const float invS = 1.0f / (SU_C - SL_C);
        const float invT = 1.0f / (TU_C - TL_C);
        const float timev = (etl * (TU_C - dt) + etu * (dt - TL_C)) * invT;
        // space = (esl*(SU-ds) + esu*(ds-SL))/(SU-SL) = C_s + B*ds
        sC[tid] = (esl * SU_C - esu * SL_C) * invS + timev;
        sB[tid] = (esu - esl) * invS;
    }

    // ---- phase 1b: haversine distances ds[k] ----
    for (int k = tid; k < KK; k += blockDim.x) {
        const int loc2 = cand[n * KK + k];
        const float lat2 = poi[2 * loc2]     * DEG2RAD;
        const float lon2 = poi[2 * loc2 + 1] * DEG2RAD;
        const float sdlat = sinf((lat2 - lat1) * 0.5f);
        const float sdlon = sinf((lon2 - lon1) * 0.5f);
        float a = sdlat * sdlat + cos_lat1 * cosf(lat2) * (sdlon * sdlon);
        a = fminf(fmaxf(a, 0.0f), 1.0f);
        sds[k] = 2.0f * R_EARTH_C * asinf(sqrtf(a));
    }
    __syncthreads();

    // ---- phase 2: outer-product write, 320MB total => HBM-bound ----
    // 250 active threads: e-pair fixed per thread (registers), k strided by 10.
    if (tid < 250) {
        const int e2 = tid % 25;        // which float2 within a k-row
        const int k0 = tid / 25;        // 0..9
        const float C0 = sC[2 * e2];
        const float C1 = sC[2 * e2 + 1];
        const float B0 = sB[2 * e2];
        const float B1 = sB[2 * e2 + 1];
        float2* __restrict__ o2 =
            (float2*)(out + (size_t)nm * (size_t)(KK * EE));
        #pragma unroll 5
        for (int k = k0; k < KK; k += 10) {
            const float d = sds[k];
            float2 v;
            v.x = fmaf(B0, d, C0);
            v.y = fmaf(B1, d, C1);
            o2[k * (EE / 2) + e2] = v;
        }
    }
}

extern "C" void kernel_launch(void* const* d_in, const int* in_sizes, int n_in,
                              void* d_out, int out_size) {
    const int*   traj_loc = (const int*)  d_in[0];
    const float* poi      = (const float*)d_in[1];
    const float* vec      = (const float*)d_in[2];
    const int*   traj_len = (const int*)  d_in[3];
    const int*   cand     = (const int*)  d_in[4];
    const float* emb_su   = (const float*)d_in[5];
    const float* emb_sl   = (const float*)d_in[6];
    const float* emb_tu   = (const float*)d_in[7];
    const float* emb_tl   = (const float*)d_in[8];
    float* out = (float*)d_out;

    embed_kernel<<<NN * MM, 256>>>(traj_loc, poi, vec, traj_len, cand,
                                   emb_su, emb_sl, emb_tu, emb_tl, out);
}

// round 2
// speedup vs baseline: 1.0481x; 1.0481x over previous
#include <cuda_runtime.h>
#include <math.h>

#define NN 32
#define MM 100
#define KK 500
#define EE 50
#define SU_C 1000.0f
#define SL_C 0.0f
#define TU_C 500.0f
#define TL_C 0.0f
#define R_EARTH_C 6371.0f
#define DEG2RAD 0.017453292519943295f

__global__ __launch_bounds__(256) void embed_kernel(
    const int* __restrict__ traj_loc,   // (N, M)
    const float* __restrict__ poi,      // (LOC, 2)
    const float* __restrict__ vec,      // (N, M)
    const int* __restrict__ traj_len,   // (N,)
    const int* __restrict__ cand,       // (N, K)
    const float* __restrict__ emb_su,   // (2, E)
    const float* __restrict__ emb_sl,   // (2, E)
    const float* __restrict__ emb_tu,   // (2, E)
    const float* __restrict__ emb_tl,   // (2, E)
    float* __restrict__ out)            // (N, M, K, E)
{
    const int nm = blockIdx.x;          // 0 .. N*M-1
    const int n = nm / MM;
    const int m = nm - n * MM;
    const int tid = threadIdx.x;

    __shared__ float sC[EE];
    __shared__ float sB[EE];
    __shared__ float sds[KK];

    // ---- per-(n,m) scalars ----
    const int loc1 = traj_loc[nm];
    const float lat1 = poi[2 * loc1]     * DEG2RAD;
    const float lon1 = poi[2 * loc1 + 1] * DEG2RAD;
    const float cos_lat1 = cosf(lat1);

    const int maskv = (m < traj_len[n]) ? 1 : 0;
    const float dt = vec[nm];

    // ---- phase 1a: coefficients C[e], B[e] ----
    if (tid < EE) {
        const float esl = emb_sl[maskv * EE + tid];
        const float esu = emb_su[maskv * EE + tid];
        const float etl = emb_tl[maskv * EE + tid];
        const float etu = emb_tu[maskv * EE + tid];
        const float invS = 1.0f / (SU_C - SL_C);
        const float invT = 1.0f / (TU_C - TL_C);
        const float timev = (etl * (TU_C - dt) + etu * (dt - TL_C)) * invT;
        // space = (esl*(SU-ds) + esu*(ds-SL))/(SU-SL) = C_s + B*ds
        sC[tid] = (esl * SU_C - esu * SL_C) * invS + timev;
        sB[tid] = (esu - esl) * invS;
    }

    // ---- phase 1b: haversine distances ds[k] ----
    for (int k = tid; k < KK; k += blockDim.x) {
        const int loc2 = cand[n * KK + k];
        const float lat2 = poi[2 * loc2]     * DEG2RAD;
        const float lon2 = poi[2 * loc2 + 1] * DEG2RAD;
        const float sdlat = sinf((lat2 - lat1) * 0.5f);
        const float sdlon = sinf((lon2 - lon1) * 0.5f);
        float a = sdlat * sdlat + cos_lat1 * cosf(lat2) * (sdlon * sdlon);
        a = fminf(fmaxf(a, 0.0f), 1.0f);
        sds[k] = 2.0f * R_EARTH_C * asinf(sqrtf(a));
    }
    __syncthreads();

    // ---- phase 2: outer-product write via STG.128 ----
    // Flat float4 view of the (K*E)=25000-float block: 6250 float4s.
    // Pattern of e-quads repeats every 2 k-rows (25 float4s). With 250 active
    // threads and stride 250, q = tid%25 is fixed per thread -> C/B in regs.
    if (tid < 250) {
        const int q   = tid % 25;       // quad position within 2-row period
        const int kp0 = tid / 25;       // k-pair base (0..9)

        const int b0 = 4 * q;
        const int e0 = (b0 + 0) % EE, e1 = (b0 + 1) % EE,
                  e2 = (b0 + 2) % EE, e3 = (b0 + 3) % EE;
        const int r0 = (b0 + 0) / EE, r1 = (b0 + 1) / EE,
                  r2 = (b0 + 2) / EE, r3 = (b0 + 3) / EE;

        const float C0 = sC[e0], C1 = sC[e1], C2 = sC[e2], C3 = sC[e3];
        const float B0 = sB[e0], B1 = sB[e1], B2 = sB[e2], B3 = sB[e3];

        float4* __restrict__ o4 =
            (float4*)(out + (size_t)nm * (size_t)(KK * EE));

        #pragma unroll 5
        for (int i = 0; i < 25; ++i) {
            const int kp = kp0 + 10 * i;            // k-pair index (0..249)
            const float dlo = sds[2 * kp];
            const float dhi = sds[2 * kp + 1];
            float4 v;
            v.x = fmaf(B0, r0 ? dhi : dlo, C0);
            v.y = fmaf(B1, r1 ? dhi : dlo, C1);
            v.z = fmaf(B2, r2 ? dhi : dlo, C2);
            v.w = fmaf(B3, r3 ? dhi : dlo, C3);
            o4[tid + 250 * i] = v;
        }
    }
}

extern "C" void kernel_launch(void* const* d_in, const int* in_sizes, int n_in,
                              void* d_out, int out_size) {
    const int*   traj_loc = (const int*)  d_in[0];
    const float* poi      = (const float*)d_in[1];
    const float* vec      = (const float*)d_in[2];
    const int*   traj_len = (const int*)  d_in[3];
    const int*   cand     = (const int*)  d_in[4];
    const float* emb_su   = (const float*)d_in[5];
    const float* emb_sl   = (const float*)d_in[6];
    const float* emb_tu   = (const float*)d_in[7];
    const float* emb_tl   = (const float*)d_in[8];
    float* out = (float*)d_out;

    embed_kernel<<<NN * MM, 256>>>(traj_loc, poi, vec, traj_len, cand,
                                   emb_su, emb_sl, emb_tu, emb_tl, out);
}